// round 15
// baseline (speedup 1.0000x reference)
#include <cuda_runtime.h>
#include <cuda_fp16.h>
#include <cstdint>
#include <cstddef>

#define BATCH   2048
#define HIDDEN  1024
#define FFN     4096
#define NEXP    8
#define TOPK    2
#define NPAIR   (BATCH * TOPK)
#define MAXMB   64
#define KSPLIT  2
#define NPCTA   304            // persistent CTAs (2 per SM)

// ---------------- device scratch ----------------
__device__ int    g_off[NEXP + 1];
__device__ int    g_num_mb;
__device__ int    g_blk_e[MAXMB];
__device__ int    g_blk_r0[MAXMB];
__device__ int    g_tok[NPAIR];
__device__ int    g_ppos[NPAIR];
__device__ float  g_w[NPAIR];
__device__ int    g_item1;                                     // G1 work queue
__device__ int    g_xready;                                    // xconv slices done
__device__ int    g_w1ready[NEXP];                             // w1 slices done/expert
__device__ __half g_xh[(size_t)BATCH * HIDDEN];                // 4 MiB
__device__ __half g_w1h[(size_t)NEXP * HIDDEN * FFN];          // 64 MiB fp16 w1
__device__ __half g_w2h[(size_t)NEXP * FFN * HIDDEN];          // 64 MiB fp16 w2
__device__ __half g_hbuf[(size_t)NPAIR * FFN];                 // 32 MiB
__device__ float  g_ybuf[(size_t)KSPLIT * NPAIR * HIDDEN];     // 32 MiB

// ---------------- helpers ----------------
__device__ __forceinline__ uint32_t smem_u32(const void* p) {
    uint32_t a;
    asm("{ .reg .u64 t; cvta.to.shared.u64 t, %1; cvt.u32.u64 %0, t; }" : "=r"(a) : "l"(p));
    return a;
}
__device__ __forceinline__ uint32_t pk_f16x2(float lo, float hi) {
    uint32_t r;
    asm("cvt.rn.f16x2.f32 %0, %1, %2;" : "=r"(r) : "f"(hi), "f"(lo));
    return r;
}
__device__ __forceinline__ void ldmx4(uint32_t* d, uint32_t addr) {
    asm volatile("ldmatrix.sync.aligned.m8n8.x4.shared.b16 {%0,%1,%2,%3}, [%4];"
                 : "=r"(d[0]), "=r"(d[1]), "=r"(d[2]), "=r"(d[3]) : "r"(addr));
}
__device__ __forceinline__ void ldmx4t(uint32_t* d, uint32_t addr) {
    asm volatile("ldmatrix.sync.aligned.m8n8.x4.trans.shared.b16 {%0,%1,%2,%3}, [%4];"
                 : "=r"(d[0]), "=r"(d[1]), "=r"(d[2]), "=r"(d[3]) : "r"(addr));
}
__device__ __forceinline__ void mma_f16(float* c, const uint32_t* a, uint32_t b0, uint32_t b1) {
    asm volatile(
        "mma.sync.aligned.m16n8k16.row.col.f32.f16.f16.f32 "
        "{%0,%1,%2,%3}, {%4,%5,%6,%7}, {%8,%9}, {%0,%1,%2,%3};"
        : "+f"(c[0]), "+f"(c[1]), "+f"(c[2]), "+f"(c[3])
        : "r"(a[0]), "r"(a[1]), "r"(a[2]), "r"(a[3]), "r"(b0), "r"(b1));
}
__device__ __forceinline__ void cpasync16(uint32_t dst, const void* src) {
    asm volatile("cp.async.cg.shared.global [%0], [%1], 16;" :: "r"(dst), "l"(src));
}

// smem per stage (32 KiB), k-tile 64:
//   As: 16 KiB fp16 [128 m][64 k]: m*128 + ((kc ^ (m&7))<<4)
//   Bs: 16 KiB at +16384 fp16 [64 k][128 n]: k*256 + ((nc ^ (k&7))<<4)
__device__ __forceinline__ uint32_t a_addr(int m, int kc) {
    return (uint32_t)(m * 128 + ((kc ^ (m & 7)) << 4));
}
__device__ __forceinline__ uint32_t b_addr(int k, int nc) {
    return (uint32_t)(16384 + k * 256 + ((nc ^ (k & 7)) << 4));
}
#define STAGE_B 32768
#define NSTAGE  3
#define SMEM_TOTAL (NSTAGE * STAGE_B)    // 96 KiB per CTA, 192 KiB per SM

// ---------------- fp32 -> fp16 slice conversion (1 MiB fp32 per slice) ----------------
__device__ __forceinline__ void conv_slice(const float* __restrict__ src,
                                           __half* __restrict__ dst, int slice) {
    const float4* s4 = reinterpret_cast<const float4*>(src) + (size_t)slice * 65536;
    uint2* d2 = reinterpret_cast<uint2*>(dst) + (size_t)slice * 65536;
#pragma unroll 1
    for (int i = threadIdx.x; i < 65536; i += 1024) {
        float4 v0 = s4[i], v1 = s4[i + 256], v2 = s4[i + 512], v3 = s4[i + 768];
        uint2 o0, o1, o2, o3;
        o0.x = pk_f16x2(v0.x, v0.y); o0.y = pk_f16x2(v0.z, v0.w);
        o1.x = pk_f16x2(v1.x, v1.y); o1.y = pk_f16x2(v1.z, v1.w);
        o2.x = pk_f16x2(v2.x, v2.y); o2.y = pk_f16x2(v2.z, v2.w);
        o3.x = pk_f16x2(v3.x, v3.y); o3.y = pk_f16x2(v3.z, v3.w);
        d2[i] = o0; d2[i + 256] = o1; d2[i + 512] = o2; d2[i + 768] = o3;
    }
}

// ---------------- routing (also resets queue state every call) ----------------
__global__ void route_kernel(const int* __restrict__ idx32, const float* __restrict__ rw) {
    __shared__ int s_cnt[NEXP];
    __shared__ int s_fill[NEXP];
    __shared__ int s_off[NEXP + 1];
    __shared__ int s_is64;
    const int tid = threadIdx.x;

    if (tid < NEXP) { s_cnt[tid] = 0; s_fill[tid] = 0; g_w1ready[tid] = 0; }
    if (tid == 0) {
        g_item1 = 0; g_xready = 0;
        int any = 0;
        for (int i = 0; i < 64; i++) any |= idx32[2 * i + 1];
        s_is64 = (any == 0) ? 1 : 0;
    }
    __syncthreads();
    const int is64 = s_is64;

    for (int i = tid; i < NPAIR; i += blockDim.x) {
        int e = is64 ? idx32[2 * i] : idx32[i];
        atomicAdd(&s_cnt[e], 1);
    }
    __syncthreads();

    if (tid == 0) {
        int acc = 0, nb = 0;
        s_off[0] = 0;
        for (int e = 0; e < NEXP; e++) {
            for (int r = 0; r < s_cnt[e]; r += 128) {
                g_blk_e[nb] = e; g_blk_r0[nb] = acc + r; nb++;
            }
            acc += s_cnt[e];
            s_off[e + 1] = acc;
        }
        g_num_mb = nb;
        for (int e = 0; e <= NEXP; e++) g_off[e] = s_off[e];
    }
    __syncthreads();

    for (int i = tid; i < NPAIR; i += blockDim.x) {
        int e = is64 ? idx32[2 * i] : idx32[i];
        int pos = s_off[e] + atomicAdd(&s_fill[e], 1);
        g_tok[pos] = i >> 1;
        g_w[pos]   = rw[i];
        g_ppos[i]  = pos;
    }
}

// ---------------- persistent GEMM1 + all conversions, one launch ----------------
// Item queue: [0,8) xconv | [8,136) w1conv (expert-major, 16/expert)
//           | [136, 136+num_mb*32) GEMM1 items | [.., +128) w2conv
// GEMM item: h[p] = silu(xh[tok(p)] @ w1h[e]); CTA tile 128x128, k-tile 64,
// 8 warps (2M x 4N), warp tile 64x32, 3-stage cp.async, 2 CTAs/SM.
__global__ __launch_bounds__(256, 2)
void moe1_persist(const float* __restrict__ X, const float* __restrict__ W1,
                  const float* __restrict__ W2) {
    extern __shared__ __align__(128) uint8_t sm[];
    __shared__ int s_item;
    const int tid = threadIdx.x;
    const int nmb = g_num_mb;
    const int gemm_end = 136 + (nmb << 5);
    const int total = gemm_end + 128;
    const uint32_t smb = smem_u32(sm);
    const int lane = tid & 31, warp = tid >> 5;
    const int wm = (warp & 1) * 64, wn = (warp >> 1) * 32;
    const int g = lane >> 3, r = lane & 7;

    for (;;) {
        __syncthreads();                       // smem/stage + s_item safety
        if (tid == 0) s_item = atomicAdd(&g_item1, 1);
        __syncthreads();
        const int it = s_item;
        if (it >= total) return;

        if (it < 8) {
            // ---- x -> fp16 slice ----
            conv_slice(X, g_xh, it);
            __syncthreads();
            if (tid == 0) { __threadfence(); atomicAdd(&g_xready, 1); }
        } else if (it < 136) {
            // ---- w1 -> fp16 slice (16 slices per expert, expert-major) ----
            const int s = it - 8;
            conv_slice(W1, g_w1h, s);
            __syncthreads();
            if (tid == 0) { __threadfence(); atomicAdd(&g_w1ready[s >> 4], 1); }
        } else if (it >= gemm_end) {
            // ---- w2 -> fp16 slice (tail filler; G2 runs next launch) ----
            conv_slice(W2, g_w2h, it - gemm_end);
        } else {
            // ================= GEMM1 item =================
            const int gi  = it - 136;
            const int mb  = gi >> 5;
            const int n0  = (gi & 31) * 128;
            const int e      = g_blk_e[mb];
            const int row0   = g_blk_r0[mb];
            const int rowEnd = g_off[e + 1];
            const __half* __restrict__ Wh = g_w1h + (size_t)e * HIDDEN * FFN;

            // readiness: all of x and this expert's w1 converted
            if (tid == 0) {
                while (atomicAdd(&g_xready, 0) < 8) { }
                while (atomicAdd(&g_w1ready[e], 0) < 16) { }
            }
            __syncthreads();

            // ---- A cp.async: 4 units/thread ----
            const __half* aP[4];
            uint32_t aoff[4];
#pragma unroll
            for (int i = 0; i < 4; i++) {
                int u = tid + i * 256;
                int m = u >> 3, kc = u & 7;
                int p = row0 + m; if (p >= rowEnd) p = rowEnd - 1;
                aP[i] = g_xh + (size_t)g_tok[p] * HIDDEN + kc * 8;
                aoff[i] = a_addr(m, kc);
            }
            // ---- B cp.async: 4 units/thread ----
            const __half* bP[4];
            uint32_t boff[4];
#pragma unroll
            for (int i = 0; i < 4; i++) {
                int u = tid + i * 256;
                int k = u >> 4, nc = u & 15;
                bP[i] = Wh + (size_t)k * FFN + n0 + nc * 8;
                boff[i] = b_addr(k, nc);
            }

            uint32_t aFrag[4], bFrag[2];
#pragma unroll
            for (int mt = 0; mt < 4; mt++)
                aFrag[mt] = a_addr(wm + mt * 16 + (g & 1) * 8 + r, (g >> 1));
#pragma unroll
            for (int ntp = 0; ntp < 2; ntp++)
                bFrag[ntp] = b_addr((g & 1) * 8 + r, (wn >> 3) + ntp * 2 + (g >> 1));

            float C[4][4][4];
#pragma unroll
            for (int a = 0; a < 4; a++)
#pragma unroll
                for (int b = 0; b < 4; b++)
#pragma unroll
                    for (int d = 0; d < 4; d++) C[a][b][d] = 0.f;

            // 3-stage pipeline over KT=16 k-tiles of 64
#pragma unroll
            for (int s = 0; s < NSTAGE - 1; s++) {
                const uint32_t sb = smb + s * STAGE_B;
                const int k0 = s * 64;
#pragma unroll
                for (int i = 0; i < 4; i++) cpasync16(sb + aoff[i], aP[i] + k0);
#pragma unroll
                for (int i = 0; i < 4; i++) cpasync16(sb + boff[i], bP[i] + (size_t)k0 * FFN);
                asm volatile("cp.async.commit_group;" ::: "memory");
            }
            int st_c = 0, st_i = NSTAGE - 1;
#pragma unroll 1
            for (int kt = 0; kt < 16; kt++) {
                asm volatile("cp.async.wait_group %0;" :: "n"(NSTAGE - 2) : "memory");
                __syncthreads();
                {
                    const uint32_t sb = smb + st_c * STAGE_B;
#pragma unroll
                    for (int ks = 0; ks < 4; ks++) {
                        uint32_t af[4][4];
#pragma unroll
                        for (int mt = 0; mt < 4; mt++)
                            ldmx4(af[mt], sb + (aFrag[mt] ^ (uint32_t)(ks << 5)));
                        uint32_t bf[2][4];
#pragma unroll
                        for (int ntp = 0; ntp < 2; ntp++)
                            ldmx4t(bf[ntp], sb + bFrag[ntp] + ks * 4096);
#pragma unroll
                        for (int mt = 0; mt < 4; mt++)
#pragma unroll
                            for (int nt = 0; nt < 4; nt++)
                                mma_f16(C[mt][nt], af[mt], bf[nt >> 1][(nt & 1) * 2],
                                        bf[nt >> 1][(nt & 1) * 2 + 1]);
                    }
                }
                if (++st_c == NSTAGE) st_c = 0;
                if (kt + NSTAGE - 1 < 16) {
                    const uint32_t sb = smb + st_i * STAGE_B;
                    const int k0 = (kt + NSTAGE - 1) * 64;
#pragma unroll
                    for (int i = 0; i < 4; i++) cpasync16(sb + aoff[i], aP[i] + k0);
#pragma unroll
                    for (int i = 0; i < 4; i++) cpasync16(sb + boff[i], bP[i] + (size_t)k0 * FFN);
                    if (++st_i == NSTAGE) st_i = 0;
                }
                asm volatile("cp.async.commit_group;" ::: "memory");
            }
            asm volatile("cp.async.wait_group 0;" ::: "memory");

            // epilogue: silu -> hbuf fp16
            const int grp = lane >> 2, tg = lane & 3;
#pragma unroll
            for (int mt = 0; mt < 4; mt++) {
#pragma unroll
                for (int half = 0; half < 2; half++) {
                    const int rowm = wm + mt * 16 + grp + half * 8;
                    const int p = row0 + rowm;
                    if (p < rowEnd) {
#pragma unroll
                        for (int nt = 0; nt < 4; nt++) {
                            float v0 = C[mt][nt][half * 2 + 0];
                            float v1 = C[mt][nt][half * 2 + 1];
                            const int col = n0 + wn + nt * 8 + 2 * tg;
                            float s0 = v0 / (1.f + __expf(-v0));
                            float s1 = v1 / (1.f + __expf(-v1));
                            *reinterpret_cast<uint32_t*>(&g_hbuf[(size_t)p * FFN + col]) =
                                pk_f16x2(s0, s1);
                        }
                    }
                }
            }
        }
    }
}

// ---------------- GEMM2 (R13 style): yb[z][p] = w(p)*(hbuf @ w2h) ----------------
template <int KT>
__global__ __launch_bounds__(256, 2)
void moe_g2(int dummy) {
    extern __shared__ __align__(128) uint8_t sm[];

    const int mb = blockIdx.x;
    if (mb >= g_num_mb) return;
    const int e      = g_blk_e[mb];
    const int row0   = g_blk_r0[mb];
    const int rowEnd = g_off[e + 1];
    const int n0     = blockIdx.y * 128;
    const int kbase  = blockIdx.z * (KT * 64);
    const __half* __restrict__ Wh = g_w2h + (size_t)e * FFN * HIDDEN + (size_t)kbase * HIDDEN;

    const int tid = threadIdx.x, lane = tid & 31, warp = tid >> 5;
    const int wm = (warp & 1) * 64, wn = (warp >> 1) * 32;
    const uint32_t smb = smem_u32(sm);

    const __half* aP[4];
    uint32_t aoff[4];
#pragma unroll
    for (int i = 0; i < 4; i++) {
        int u = tid + i * 256;
        int m = u >> 3, kc = u & 7;
        int p = row0 + m; if (p >= rowEnd) p = rowEnd - 1;
        aP[i] = g_hbuf + (size_t)p * FFN + kbase + kc * 8;
        aoff[i] = a_addr(m, kc);
    }
    const __half* bP[4];
    uint32_t boff[4];
#pragma unroll
    for (int i = 0; i < 4; i++) {
        int u = tid + i * 256;
        int k = u >> 4, nc = u & 15;
        bP[i] = Wh + (size_t)k * HIDDEN + n0 + nc * 8;
        boff[i] = b_addr(k, nc);
    }

    const int g = lane >> 3, r = lane & 7;
    uint32_t aFrag[4], bFrag[2];
#pragma unroll
    for (int mt = 0; mt < 4; mt++)
        aFrag[mt] = a_addr(wm + mt * 16 + (g & 1) * 8 + r, (g >> 1));
#pragma unroll
    for (int ntp = 0; ntp < 2; ntp++)
        bFrag[ntp] = b_addr((g & 1) * 8 + r, (wn >> 3) + ntp * 2 + (g >> 1));

    float C[4][4][4];
#pragma unroll
    for (int a = 0; a < 4; a++)
#pragma unroll
        for (int b = 0; b < 4; b++)
#pragma unroll
            for (int d = 0; d < 4; d++) C[a][b][d] = 0.f;

#pragma unroll
    for (int s = 0; s < NSTAGE - 1; s++) {
        const uint32_t sb = smb + s * STAGE_B;
        const int k0 = s * 64;
#pragma unroll
        for (int i = 0; i < 4; i++) cpasync16(sb + aoff[i], aP[i] + k0);
#pragma unroll
        for (int i = 0; i < 4; i++) cpasync16(sb + boff[i], bP[i] + (size_t)k0 * HIDDEN);
        asm volatile("cp.async.commit_group;" ::: "memory");
    }
    int st_c = 0, st_i = NSTAGE - 1;
#pragma unroll 1
    for (int kt = 0; kt < KT; kt++) {
        asm volatile("cp.async.wait_group %0;" :: "n"(NSTAGE - 2) : "memory");
        __syncthreads();
        {
            const uint32_t sb = smb + st_c * STAGE_B;
#pragma unroll
            for (int ks = 0; ks < 4; ks++) {
                uint32_t af[4][4];
#pragma unroll
                for (int mt = 0; mt < 4; mt++)
                    ldmx4(af[mt], sb + (aFrag[mt] ^ (uint32_t)(ks << 5)));
                uint32_t bf[2][4];
#pragma unroll
                for (int ntp = 0; ntp < 2; ntp++)
                    ldmx4t(bf[ntp], sb + bFrag[ntp] + ks * 4096);
#pragma unroll
                for (int mt = 0; mt < 4; mt++)
#pragma unroll
                    for (int nt = 0; nt < 4; nt++)
                        mma_f16(C[mt][nt], af[mt], bf[nt >> 1][(nt & 1) * 2],
                                bf[nt >> 1][(nt & 1) * 2 + 1]);
            }
        }
        if (++st_c == NSTAGE) st_c = 0;
        if (kt + NSTAGE - 1 < KT) {
            const uint32_t sb = smb + st_i * STAGE_B;
            const int k0 = (kt + NSTAGE - 1) * 64;
#pragma unroll
            for (int i = 0; i < 4; i++) cpasync16(sb + aoff[i], aP[i] + k0);
#pragma unroll
            for (int i = 0; i < 4; i++) cpasync16(sb + boff[i], bP[i] + (size_t)k0 * HIDDEN);
            if (++st_i == NSTAGE) st_i = 0;
        }
        asm volatile("cp.async.commit_group;" ::: "memory");
    }

    const int grp = lane >> 2, tg = lane & 3;
#pragma unroll
    for (int mt = 0; mt < 4; mt++) {
#pragma unroll
        for (int half = 0; half < 2; half++) {
            const int rowm = wm + mt * 16 + grp + half * 8;
            const int p = row0 + rowm;
            if (p < rowEnd) {
                const float wgt = g_w[p];
#pragma unroll
                for (int nt = 0; nt < 4; nt++) {
                    float v0 = C[mt][nt][half * 2 + 0];
                    float v1 = C[mt][nt][half * 2 + 1];
                    const int col = n0 + wn + nt * 8 + 2 * tg;
                    float* dst = g_ybuf + ((size_t)blockIdx.z * NPAIR + p) * HIDDEN + col;
                    *reinterpret_cast<float2*>(dst) = make_float2(v0 * wgt, v1 * wgt);
                }
            }
        }
    }
}

// ---------------- combine ----------------
__global__ void combine_kernel(float* __restrict__ out) {
    const int t = blockIdx.x;
    const int c = threadIdx.x * 4;
    const int p0 = g_ppos[2 * t], p1 = g_ppos[2 * t + 1];
    float4 acc = make_float4(0.f, 0.f, 0.f, 0.f);
#pragma unroll
    for (int s = 0; s < KSPLIT; s++) {
        const float4 a = *reinterpret_cast<const float4*>(
            g_ybuf + ((size_t)s * NPAIR + p0) * HIDDEN + c);
        const float4 b = *reinterpret_cast<const float4*>(
            g_ybuf + ((size_t)s * NPAIR + p1) * HIDDEN + c);
        acc.x += a.x + b.x; acc.y += a.y + b.y;
        acc.z += a.z + b.z; acc.w += a.w + b.w;
    }
    *reinterpret_cast<float4*>(out + (size_t)t * HIDDEN + c) = acc;
}

// ---------------- launch ----------------
extern "C" void kernel_launch(void* const* d_in, const int* in_sizes, int n_in,
                              void* d_out, int out_size) {
    const float* x   = (const float*)d_in[0];
    const float* rw  = (const float*)d_in[1];
    const float* w1  = (const float*)d_in[2];
    const float* w2  = (const float*)d_in[3];
    const int*   idx = (const int*)d_in[4];
    float* out = (float*)d_out;

    cudaFuncSetAttribute(moe1_persist, cudaFuncAttributeMaxDynamicSharedMemorySize, SMEM_TOTAL);
    cudaFuncSetAttribute(moe_g2<32>, cudaFuncAttributeMaxDynamicSharedMemorySize, SMEM_TOTAL);

    route_kernel<<<1, 256>>>(idx, rw);
    moe1_persist<<<NPCTA, 256, SMEM_TOTAL>>>(x, w1, w2);
    moe_g2<32><<<dim3(40, HIDDEN / 128, KSPLIT), 256, SMEM_TOTAL>>>(0);
    combine_kernel<<<BATCH, 256>>>(out);
}

// round 16
// speedup vs baseline: 1.0118x; 1.0118x over previous
#include <cuda_runtime.h>
#include <cuda_fp16.h>
#include <cstdint>
#include <cstddef>

#define BATCH   2048
#define HIDDEN  1024
#define FFN     4096
#define NEXP    8
#define TOPK    2
#define NPAIR   (BATCH * TOPK)
#define MAXMB   64
#define KSPLIT  2

// ---------------- device scratch ----------------
__device__ int    g_off[NEXP + 1];
__device__ int    g_num_mb;
__device__ int    g_blk_e[MAXMB];
__device__ int    g_blk_r0[MAXMB];
__device__ int    g_tok[NPAIR];
__device__ int    g_ppos[NPAIR];
__device__ float  g_w[NPAIR];
__device__ int    g_xready;                                    // xconv slices done (8)
__device__ int    g_w1ready[NEXP];                             // w1 slices done (16/expert)
__device__ __half g_xh[(size_t)BATCH * HIDDEN];                // 4 MiB
__device__ __half g_w1h[(size_t)NEXP * HIDDEN * FFN];          // 64 MiB fp16 w1
__device__ __half g_w2h[(size_t)NEXP * FFN * HIDDEN];          // 64 MiB fp16 w2
__device__ __half g_hbuf[(size_t)NPAIR * FFN];                 // 32 MiB
__device__ float  g_ybuf[(size_t)KSPLIT * NPAIR * HIDDEN];     // 32 MiB

// ---------------- helpers ----------------
__device__ __forceinline__ uint32_t smem_u32(const void* p) {
    uint32_t a;
    asm("{ .reg .u64 t; cvta.to.shared.u64 t, %1; cvt.u32.u64 %0, t; }" : "=r"(a) : "l"(p));
    return a;
}
__device__ __forceinline__ uint32_t pk_f16x2(float lo, float hi) {
    uint32_t r;
    asm("cvt.rn.f16x2.f32 %0, %1, %2;" : "=r"(r) : "f"(hi), "f"(lo));
    return r;
}
__device__ __forceinline__ void ldmx4(uint32_t* d, uint32_t addr) {
    asm volatile("ldmatrix.sync.aligned.m8n8.x4.shared.b16 {%0,%1,%2,%3}, [%4];"
                 : "=r"(d[0]), "=r"(d[1]), "=r"(d[2]), "=r"(d[3]) : "r"(addr));
}
__device__ __forceinline__ void ldmx4t(uint32_t* d, uint32_t addr) {
    asm volatile("ldmatrix.sync.aligned.m8n8.x4.trans.shared.b16 {%0,%1,%2,%3}, [%4];"
                 : "=r"(d[0]), "=r"(d[1]), "=r"(d[2]), "=r"(d[3]) : "r"(addr));
}
__device__ __forceinline__ void mma_f16(float* c, const uint32_t* a, uint32_t b0, uint32_t b1) {
    asm volatile(
        "mma.sync.aligned.m16n8k16.row.col.f32.f16.f16.f32 "
        "{%0,%1,%2,%3}, {%4,%5,%6,%7}, {%8,%9}, {%0,%1,%2,%3};"
        : "+f"(c[0]), "+f"(c[1]), "+f"(c[2]), "+f"(c[3])
        : "r"(a[0]), "r"(a[1]), "r"(a[2]), "r"(a[3]), "r"(b0), "r"(b1));
}
__device__ __forceinline__ void cpasync16(uint32_t dst, const void* src) {
    asm volatile("cp.async.cg.shared.global [%0], [%1], 16;" :: "r"(dst), "l"(src));
}

// smem per stage (32 KiB), k-tile 64:
//   As: 16 KiB fp16 [128 m][64 k]: m*128 + ((kc ^ (m&7))<<4)
//   Bs: 16 KiB at +16384 fp16 [64 k][128 n]: k*256 + ((nc ^ (k&7))<<4)
__device__ __forceinline__ uint32_t a_addr(int m, int kc) {
    return (uint32_t)(m * 128 + ((kc ^ (m & 7)) << 4));
}
__device__ __forceinline__ uint32_t b_addr(int k, int nc) {
    return (uint32_t)(16384 + k * 256 + ((nc ^ (k & 7)) << 4));
}
#define STAGE_B 32768
#define NSTAGE  3
#define SMEM_TOTAL (NSTAGE * STAGE_B)    // 96 KiB per CTA, 192 KiB per SM

// ---------------- fp32 -> fp16 slice conversion (65536 float4 per slice) ----------------
__device__ __forceinline__ void conv_slice(const float* __restrict__ src,
                                           __half* __restrict__ dst, int slice) {
    const float4* s4 = reinterpret_cast<const float4*>(src) + (size_t)slice * 65536;
    uint2* d2 = reinterpret_cast<uint2*>(dst) + (size_t)slice * 65536;
#pragma unroll 1
    for (int i = threadIdx.x; i < 65536; i += 1024) {
        float4 v0 = s4[i], v1 = s4[i + 256], v2 = s4[i + 512], v3 = s4[i + 768];
        uint2 o0, o1, o2, o3;
        o0.x = pk_f16x2(v0.x, v0.y); o0.y = pk_f16x2(v0.z, v0.w);
        o1.x = pk_f16x2(v1.x, v1.y); o1.y = pk_f16x2(v1.z, v1.w);
        o2.x = pk_f16x2(v2.x, v2.y); o2.y = pk_f16x2(v2.z, v2.w);
        o3.x = pk_f16x2(v3.x, v3.y); o3.y = pk_f16x2(v3.z, v3.w);
        d2[i] = o0; d2[i + 256] = o1; d2[i + 512] = o2; d2[i + 768] = o3;
    }
}

// ---------------- routing (resets readiness flags every call) ----------------
__global__ void route_kernel(const int* __restrict__ idx32, const float* __restrict__ rw) {
    __shared__ int s_cnt[NEXP];
    __shared__ int s_fill[NEXP];
    __shared__ int s_off[NEXP + 1];
    __shared__ int s_is64;
    const int tid = threadIdx.x;

    if (tid < NEXP) { s_cnt[tid] = 0; s_fill[tid] = 0; g_w1ready[tid] = 0; }
    if (tid == 0) {
        g_xready = 0;
        int any = 0;
        for (int i = 0; i < 64; i++) any |= idx32[2 * i + 1];
        s_is64 = (any == 0) ? 1 : 0;
    }
    __syncthreads();
    const int is64 = s_is64;

    for (int i = tid; i < NPAIR; i += blockDim.x) {
        int e = is64 ? idx32[2 * i] : idx32[i];
        atomicAdd(&s_cnt[e], 1);
    }
    __syncthreads();

    if (tid == 0) {
        int acc = 0, nb = 0;
        s_off[0] = 0;
        for (int e = 0; e < NEXP; e++) {
            for (int r = 0; r < s_cnt[e]; r += 128) {
                g_blk_e[nb] = e; g_blk_r0[nb] = acc + r; nb++;
            }
            acc += s_cnt[e];
            s_off[e + 1] = acc;
        }
        g_num_mb = nb;
        for (int e = 0; e <= NEXP; e++) g_off[e] = s_off[e];
    }
    __syncthreads();

    for (int i = tid; i < NPAIR; i += blockDim.x) {
        int e = is64 ? idx32[2 * i] : idx32[i];
        int pos = s_off[e] + atomicAdd(&s_fill[e], 1);
        g_tok[pos] = i >> 1;
        g_w[pos]   = rw[i];
        g_ppos[i]  = pos;
    }
}

// ---------------- fused conv + GEMM1, single 1-D grid of 1544 blocks ----------------
// ids [0,8):    xconv slices  (lowest ids -> resident in wave 1, no deadlock)
// ids [8,136):  w1conv slices (expert-major, 16 per expert)
// ids [136,1544): j = id-136 in [0,1408): j%11==10 -> w2conv slice j/11 (128 total),
//                 else GEMM1 item g = j - (j+1)/11: mb = g>>5, n0 = (g&31)*128.
// GEMM: h[p] = silu(xh[tok(p)] @ w1h[e]); spins on xready/w1ready[e] first.
__global__ __launch_bounds__(256, 2)
void moe1_fused(const float* __restrict__ X, const float* __restrict__ W1,
                const float* __restrict__ W2) {
    const int bid = blockIdx.x;
    const int tid = threadIdx.x;

    if (bid < 8) {
        conv_slice(X, g_xh, bid);
        __syncthreads();
        if (tid == 0) { __threadfence(); atomicAdd(&g_xready, 1); }
        return;
    }
    if (bid < 136) {
        const int s = bid - 8;
        conv_slice(W1, g_w1h, s);
        __syncthreads();
        if (tid == 0) { __threadfence(); atomicAdd(&g_w1ready[s >> 4], 1); }
        return;
    }
    const int j = bid - 136;
    if (j % 11 == 10) {
        conv_slice(W2, g_w2h, j / 11);
        return;
    }
    const int gidx = j - (j + 1) / 11;
    const int mb = gidx >> 5;
    if (mb >= g_num_mb) return;
    const int n0     = (gidx & 31) * 128;
    const int e      = g_blk_e[mb];
    const int row0   = g_blk_r0[mb];
    const int rowEnd = g_off[e + 1];
    const __half* __restrict__ Wh = g_w1h + (size_t)e * HIDDEN * FFN;

    // ---- wait for conversion dependencies (L2 volatile poll, tid 0 only) ----
    if (tid == 0) {
        while (*(volatile const int*)&g_xready < 8)
            asm volatile("nanosleep.u32 128;");
        while (*(volatile const int*)&g_w1ready[e] < 16)
            asm volatile("nanosleep.u32 128;");
    }
    __syncthreads();

    extern __shared__ __align__(128) uint8_t sm[];
    const uint32_t smb = smem_u32(sm);
    const int lane = tid & 31, warp = tid >> 5;
    const int wm = (warp & 1) * 64, wn = (warp >> 1) * 32;

    // ---- A cp.async: 4 units/thread ----
    const __half* aP[4];
    uint32_t aoff[4];
#pragma unroll
    for (int i = 0; i < 4; i++) {
        int u = tid + i * 256;
        int m = u >> 3, kc = u & 7;
        int p = row0 + m; if (p >= rowEnd) p = rowEnd - 1;
        aP[i] = g_xh + (size_t)g_tok[p] * HIDDEN + kc * 8;
        aoff[i] = a_addr(m, kc);
    }
    // ---- B cp.async: 4 units/thread ----
    const __half* bP[4];
    uint32_t boff[4];
#pragma unroll
    for (int i = 0; i < 4; i++) {
        int u = tid + i * 256;
        int k = u >> 4, nc = u & 15;
        bP[i] = Wh + (size_t)k * FFN + n0 + nc * 8;
        boff[i] = b_addr(k, nc);
    }

    const int g = lane >> 3, r = lane & 7;
    uint32_t aFrag[4], bFrag[2];
#pragma unroll
    for (int mt = 0; mt < 4; mt++)
        aFrag[mt] = a_addr(wm + mt * 16 + (g & 1) * 8 + r, (g >> 1));
#pragma unroll
    for (int ntp = 0; ntp < 2; ntp++)
        bFrag[ntp] = b_addr((g & 1) * 8 + r, (wn >> 3) + ntp * 2 + (g >> 1));

    float C[4][4][4];
#pragma unroll
    for (int a = 0; a < 4; a++)
#pragma unroll
        for (int b = 0; b < 4; b++)
#pragma unroll
            for (int d = 0; d < 4; d++) C[a][b][d] = 0.f;

    // ---- 3-stage pipeline over KT=16 k-tiles of 64 ----
#pragma unroll
    for (int s = 0; s < NSTAGE - 1; s++) {
        const uint32_t sb = smb + s * STAGE_B;
        const int k0 = s * 64;
#pragma unroll
        for (int i = 0; i < 4; i++) cpasync16(sb + aoff[i], aP[i] + k0);
#pragma unroll
        for (int i = 0; i < 4; i++) cpasync16(sb + boff[i], bP[i] + (size_t)k0 * FFN);
        asm volatile("cp.async.commit_group;" ::: "memory");
    }
    int st_c = 0, st_i = NSTAGE - 1;
#pragma unroll 1
    for (int kt = 0; kt < 16; kt++) {
        asm volatile("cp.async.wait_group %0;" :: "n"(NSTAGE - 2) : "memory");
        __syncthreads();
        {
            const uint32_t sb = smb + st_c * STAGE_B;
#pragma unroll
            for (int ks = 0; ks < 4; ks++) {
                uint32_t af[4][4];
#pragma unroll
                for (int mt = 0; mt < 4; mt++)
                    ldmx4(af[mt], sb + (aFrag[mt] ^ (uint32_t)(ks << 5)));
                uint32_t bf[2][4];
#pragma unroll
                for (int ntp = 0; ntp < 2; ntp++)
                    ldmx4t(bf[ntp], sb + bFrag[ntp] + ks * 4096);
#pragma unroll
                for (int mt = 0; mt < 4; mt++)
#pragma unroll
                    for (int nt = 0; nt < 4; nt++)
                        mma_f16(C[mt][nt], af[mt], bf[nt >> 1][(nt & 1) * 2],
                                bf[nt >> 1][(nt & 1) * 2 + 1]);
            }
        }
        if (++st_c == NSTAGE) st_c = 0;
        if (kt + NSTAGE - 1 < 16) {
            const uint32_t sb = smb + st_i * STAGE_B;
            const int k0 = (kt + NSTAGE - 1) * 64;
#pragma unroll
            for (int i = 0; i < 4; i++) cpasync16(sb + aoff[i], aP[i] + k0);
#pragma unroll
            for (int i = 0; i < 4; i++) cpasync16(sb + boff[i], bP[i] + (size_t)k0 * FFN);
            if (++st_i == NSTAGE) st_i = 0;
        }
        asm volatile("cp.async.commit_group;" ::: "memory");
    }
    asm volatile("cp.async.wait_group 0;" ::: "memory");

    // ---- epilogue: silu -> hbuf fp16 ----
    const int grp = lane >> 2, tg = lane & 3;
#pragma unroll
    for (int mt = 0; mt < 4; mt++) {
#pragma unroll
        for (int half = 0; half < 2; half++) {
            const int rowm = wm + mt * 16 + grp + half * 8;
            const int p = row0 + rowm;
            if (p < rowEnd) {
#pragma unroll
                for (int nt = 0; nt < 4; nt++) {
                    float v0 = C[mt][nt][half * 2 + 0];
                    float v1 = C[mt][nt][half * 2 + 1];
                    const int col = n0 + wn + nt * 8 + 2 * tg;
                    float s0 = v0 / (1.f + __expf(-v0));
                    float s1 = v1 / (1.f + __expf(-v1));
                    *reinterpret_cast<uint32_t*>(&g_hbuf[(size_t)p * FFN + col]) =
                        pk_f16x2(s0, s1);
                }
            }
        }
    }
}

// ---------------- GEMM2: yb[z][p] = w(p)*(hbuf[p, z*2048:+2048] @ w2h[e][...]) ----------------
template <int KT>
__global__ __launch_bounds__(256, 2)
void moe_g2(int dummy) {
    extern __shared__ __align__(128) uint8_t sm[];

    const int mb = blockIdx.x;
    if (mb >= g_num_mb) return;
    const int e      = g_blk_e[mb];
    const int row0   = g_blk_r0[mb];
    const int rowEnd = g_off[e + 1];
    const int n0     = blockIdx.y * 128;
    const int kbase  = blockIdx.z * (KT * 64);
    const __half* __restrict__ Wh = g_w2h + (size_t)e * FFN * HIDDEN + (size_t)kbase * HIDDEN;

    const int tid = threadIdx.x, lane = tid & 31, warp = tid >> 5;
    const int wm = (warp & 1) * 64, wn = (warp >> 1) * 32;
    const uint32_t smb = smem_u32(sm);

    const __half* aP[4];
    uint32_t aoff[4];
#pragma unroll
    for (int i = 0; i < 4; i++) {
        int u = tid + i * 256;
        int m = u >> 3, kc = u & 7;
        int p = row0 + m; if (p >= rowEnd) p = rowEnd - 1;
        aP[i] = g_hbuf + (size_t)p * FFN + kbase + kc * 8;
        aoff[i] = a_addr(m, kc);
    }
    const __half* bP[4];
    uint32_t boff[4];
#pragma unroll
    for (int i = 0; i < 4; i++) {
        int u = tid + i * 256;
        int k = u >> 4, nc = u & 15;
        bP[i] = Wh + (size_t)k * HIDDEN + n0 + nc * 8;
        boff[i] = b_addr(k, nc);
    }

    const int g = lane >> 3, r = lane & 7;
    uint32_t aFrag[4], bFrag[2];
#pragma unroll
    for (int mt = 0; mt < 4; mt++)
        aFrag[mt] = a_addr(wm + mt * 16 + (g & 1) * 8 + r, (g >> 1));
#pragma unroll
    for (int ntp = 0; ntp < 2; ntp++)
        bFrag[ntp] = b_addr((g & 1) * 8 + r, (wn >> 3) + ntp * 2 + (g >> 1));

    float C[4][4][4];
#pragma unroll
    for (int a = 0; a < 4; a++)
#pragma unroll
        for (int b = 0; b < 4; b++)
#pragma unroll
            for (int d = 0; d < 4; d++) C[a][b][d] = 0.f;

#pragma unroll
    for (int s = 0; s < NSTAGE - 1; s++) {
        const uint32_t sb = smb + s * STAGE_B;
        const int k0 = s * 64;
#pragma unroll
        for (int i = 0; i < 4; i++) cpasync16(sb + aoff[i], aP[i] + k0);
#pragma unroll
        for (int i = 0; i < 4; i++) cpasync16(sb + boff[i], bP[i] + (size_t)k0 * HIDDEN);
        asm volatile("cp.async.commit_group;" ::: "memory");
    }
    int st_c = 0, st_i = NSTAGE - 1;
#pragma unroll 1
    for (int kt = 0; kt < KT; kt++) {
        asm volatile("cp.async.wait_group %0;" :: "n"(NSTAGE - 2) : "memory");
        __syncthreads();
        {
            const uint32_t sb = smb + st_c * STAGE_B;
#pragma unroll
            for (int ks = 0; ks < 4; ks++) {
                uint32_t af[4][4];
#pragma unroll
                for (int mt = 0; mt < 4; mt++)
                    ldmx4(af[mt], sb + (aFrag[mt] ^ (uint32_t)(ks << 5)));
                uint32_t bf[2][4];
#pragma unroll
                for (int ntp = 0; ntp < 2; ntp++)
                    ldmx4t(bf[ntp], sb + bFrag[ntp] + ks * 4096);
#pragma unroll
                for (int mt = 0; mt < 4; mt++)
#pragma unroll
                    for (int nt = 0; nt < 4; nt++)
                        mma_f16(C[mt][nt], af[mt], bf[nt >> 1][(nt & 1) * 2],
                                bf[nt >> 1][(nt & 1) * 2 + 1]);
            }
        }
        if (++st_c == NSTAGE) st_c = 0;
        if (kt + NSTAGE - 1 < KT) {
            const uint32_t sb = smb + st_i * STAGE_B;
            const int k0 = (kt + NSTAGE - 1) * 64;
#pragma unroll
            for (int i = 0; i < 4; i++) cpasync16(sb + aoff[i], aP[i] + k0);
#pragma unroll
            for (int i = 0; i < 4; i++) cpasync16(sb + boff[i], bP[i] + (size_t)k0 * HIDDEN);
            if (++st_i == NSTAGE) st_i = 0;
        }
        asm volatile("cp.async.commit_group;" ::: "memory");
    }

    const int grp = lane >> 2, tg = lane & 3;
#pragma unroll
    for (int mt = 0; mt < 4; mt++) {
#pragma unroll
        for (int half = 0; half < 2; half++) {
            const int rowm = wm + mt * 16 + grp + half * 8;
            const int p = row0 + rowm;
            if (p < rowEnd) {
                const float wgt = g_w[p];
#pragma unroll
                for (int nt = 0; nt < 4; nt++) {
                    float v0 = C[mt][nt][half * 2 + 0];
                    float v1 = C[mt][nt][half * 2 + 1];
                    const int col = n0 + wn + nt * 8 + 2 * tg;
                    float* dst = g_ybuf + ((size_t)blockIdx.z * NPAIR + p) * HIDDEN + col;
                    *reinterpret_cast<float2*>(dst) = make_float2(v0 * wgt, v1 * wgt);
                }
            }
        }
    }
}

// ---------------- combine ----------------
__global__ void combine_kernel(float* __restrict__ out) {
    const int t = blockIdx.x;
    const int c = threadIdx.x * 4;
    const int p0 = g_ppos[2 * t], p1 = g_ppos[2 * t + 1];
    float4 acc = make_float4(0.f, 0.f, 0.f, 0.f);
#pragma unroll
    for (int s = 0; s < KSPLIT; s++) {
        const float4 a = *reinterpret_cast<const float4*>(
            g_ybuf + ((size_t)s * NPAIR + p0) * HIDDEN + c);
        const float4 b = *reinterpret_cast<const float4*>(
            g_ybuf + ((size_t)s * NPAIR + p1) * HIDDEN + c);
        acc.x += a.x + b.x; acc.y += a.y + b.y;
        acc.z += a.z + b.z; acc.w += a.w + b.w;
    }
    *reinterpret_cast<float4*>(out + (size_t)t * HIDDEN + c) = acc;
}

// ---------------- launch ----------------
extern "C" void kernel_launch(void* const* d_in, const int* in_sizes, int n_in,
                              void* d_out, int out_size) {
    const float* x   = (const float*)d_in[0];
    const float* rw  = (const float*)d_in[1];
    const float* w1  = (const float*)d_in[2];
    const float* w2  = (const float*)d_in[3];
    const int*   idx = (const int*)d_in[4];
    float* out = (float*)d_out;

    cudaFuncSetAttribute(moe1_fused, cudaFuncAttributeMaxDynamicSharedMemorySize, SMEM_TOTAL);
    cudaFuncSetAttribute(moe_g2<32>, cudaFuncAttributeMaxDynamicSharedMemorySize, SMEM_TOTAL);

    route_kernel<<<1, 256>>>(idx, rw);
    moe1_fused<<<1544, 256, SMEM_TOTAL>>>(x, w1, w2);
    moe_g2<32><<<dim3(40, HIDDEN / 128, KSPLIT), 256, SMEM_TOTAL>>>(0);
    combine_kernel<<<BATCH, 256>>>(out);
}